// round 1
// baseline (speedup 1.0000x reference)
#include <cuda_runtime.h>
#include <math.h>

// Problem constants
#define B_    4
#define S_    4096
#define H_    2048
#define DFF_  8192
#define NTOK  (B_*S_)      // 16384 tokens
#define KCAP  (S_/2)       // top-k k = 2048
#define EPSF  1e-5f

// ---------------- static device scratch (allocation-free rule) ----------------
__device__ float g_weights[NTOK];
__device__ float g_rstd1[NTOK];
__device__ float g_thresh[B_];
__device__ int   g_selidx[NTOK];
__device__ int   g_count;

__device__ float g_bufA[(size_t)NTOK * H_];     // n1 compact, then n2 compact
__device__ float g_attn[(size_t)NTOK * H_];     // attn_out compact
__device__ float g_wvwo[(size_t)H_ * H_];       // Wv @ Wo
__device__ float g_gate[(size_t)NTOK * DFF_];   // gate proj, then h = silu(g)*u
__device__ float g_up  [(size_t)NTOK * DFF_];   // up proj

// ---------------- small kernels ----------------

__global__ void reset_kernel() { g_count = 0; }

// One block per token: router logit + sigmoid weight + rmsnorm1 rstd
__global__ void router_kernel(const float* __restrict__ x,
                              const float* __restrict__ wr,
                              const float* __restrict__ br) {
    int t = blockIdx.x;
    const float4* x4 = (const float4*)(x + (size_t)t * H_);
    const float4* w4 = (const float4*)wr;
    float dot = 0.f, ss = 0.f;
    for (int i = threadIdx.x; i < H_/4; i += blockDim.x) {
        float4 xv = x4[i], wv = w4[i];
        dot += xv.x*wv.x + xv.y*wv.y + xv.z*wv.z + xv.w*wv.w;
        ss  += xv.x*xv.x + xv.y*xv.y + xv.z*xv.z + xv.w*xv.w;
    }
    __shared__ float sd[256], sq[256];
    sd[threadIdx.x] = dot; sq[threadIdx.x] = ss;
    __syncthreads();
    for (int s = 128; s > 0; s >>= 1) {
        if (threadIdx.x < s) { sd[threadIdx.x] += sd[threadIdx.x+s]; sq[threadIdx.x] += sq[threadIdx.x+s]; }
        __syncthreads();
    }
    if (threadIdx.x == 0) {
        float l = sd[0] + br[0];
        g_weights[t] = 1.f / (1.f + expf(-l));
        g_rstd1[t]   = rsqrtf(sq[0] / (float)H_ + EPSF);
    }
}

// One block per batch: bitonic sort 4096 weights descending in smem, pick k-th
__global__ void thresh_kernel() {
    __shared__ float s[S_];
    int b = blockIdx.x;
    for (int i = threadIdx.x; i < S_; i += blockDim.x) s[i] = g_weights[(size_t)b * S_ + i];
    __syncthreads();
    for (int k = 2; k <= S_; k <<= 1) {
        for (int j = k >> 1; j > 0; j >>= 1) {
            for (int i = threadIdx.x; i < S_; i += blockDim.x) {
                int ixj = i ^ j;
                if (ixj > i) {
                    float a = s[i], c = s[ixj];
                    bool desc = ((i & k) == 0);
                    if (desc ? (a < c) : (a > c)) { s[i] = c; s[ixj] = a; }
                }
            }
            __syncthreads();
        }
    }
    if (threadIdx.x == 0) g_thresh[b] = s[KCAP - 1];
}

// Build compacted selected-token list (order irrelevant; per-token work independent)
__global__ void select_kernel() {
    int t = blockIdx.x * blockDim.x + threadIdx.x;
    if (t >= NTOK) return;
    if (g_weights[t] >= g_thresh[t / S_]) {
        int p = atomicAdd(&g_count, 1);
        g_selidx[p] = t;
    }
}

// Unselected tokens: out = x
__global__ void copyx_kernel(const float* __restrict__ x, float* __restrict__ out) {
    int t = blockIdx.x;
    if (g_weights[t] >= g_thresh[t / S_]) return;
    const float4* x4 = (const float4*)(x + (size_t)t * H_);
    float4* o4 = (float4*)(out + (size_t)t * H_);
    for (int i = threadIdx.x; i < H_/4; i += blockDim.x) o4[i] = x4[i];
}

// Gather n1 = rmsnorm(x)*norm1_w into compact rows
__global__ void gather_kernel(const float* __restrict__ x, const float* __restrict__ n1w) {
    int r = blockIdx.x;
    if (r >= g_count) return;
    int t = g_selidx[r];
    float rs = g_rstd1[t];
    const float4* x4 = (const float4*)(x + (size_t)t * H_);
    const float4* w4 = (const float4*)n1w;
    float4* o4 = (float4*)(g_bufA + (size_t)r * H_);
    for (int i = threadIdx.x; i < H_/4; i += blockDim.x) {
        float4 xv = x4[i], wv = w4[i];
        o4[i] = make_float4(xv.x*rs*wv.x, xv.y*rs*wv.y, xv.z*rs*wv.z, xv.w*rs*wv.w);
    }
}

// res = x + attn; out[token] = res; bufA = rmsnorm(res)*norm2_w (compact)
__global__ void res_kernel(const float* __restrict__ x, const float* __restrict__ n2w,
                           float* __restrict__ out) {
    int r = blockIdx.x;
    if (r >= g_count) return;
    int t = g_selidx[r];
    __shared__ float sres[H_];
    __shared__ float red[256];
    const float4* x4 = (const float4*)(x + (size_t)t * H_);
    const float4* a4 = (const float4*)(g_attn + (size_t)r * H_);
    float ss = 0.f;
    for (int i = threadIdx.x; i < H_/4; i += blockDim.x) {
        float4 xv = x4[i], av = a4[i];
        float4 rv = make_float4(xv.x+av.x, xv.y+av.y, xv.z+av.z, xv.w+av.w);
        ((float4*)sres)[i] = rv;
        ss += rv.x*rv.x + rv.y*rv.y + rv.z*rv.z + rv.w*rv.w;
    }
    red[threadIdx.x] = ss;
    __syncthreads();
    for (int s = 128; s > 0; s >>= 1) {
        if (threadIdx.x < s) red[threadIdx.x] += red[threadIdx.x+s];
        __syncthreads();
    }
    float rstd = rsqrtf(red[0] / (float)H_ + EPSF);
    float4* o4 = (float4*)(out + (size_t)t * H_);
    float4* n4 = (float4*)(g_bufA + (size_t)r * H_);
    const float4* w4 = (const float4*)n2w;
    for (int i = threadIdx.x; i < H_/4; i += blockDim.x) {
        float4 rv = ((float4*)sres)[i];
        float4 wv = w4[i];
        o4[i] = rv;
        n4[i] = make_float4(rv.x*rstd*wv.x, rv.y*rstd*wv.y, rv.z*rstd*wv.z, rv.w*rstd*wv.w);
    }
}

// h = silu(gate) * up, in place into g_gate
__global__ void swiglu_kernel() {
    size_t n4 = (size_t)g_count * (DFF_/4);
    size_t i = (size_t)blockIdx.x * blockDim.x + threadIdx.x;
    if (i >= n4) return;
    float4 g = ((const float4*)g_gate)[i];
    float4 u = ((const float4*)g_up)[i];
    float4 h;
    h.x = g.x / (1.f + expf(-g.x)) * u.x;
    h.y = g.y / (1.f + expf(-g.y)) * u.y;
    h.z = g.z / (1.f + expf(-g.z)) * u.z;
    h.w = g.w / (1.f + expf(-g.w)) * u.w;
    ((float4*)g_gate)[i] = h;
}

// ---------------- tiled fp32 GEMM: C[M,N] = A[M,K] @ B[K,N], row-major ----------------
// 128x128 tile, TK=8, 256 threads, 8x8 per-thread microtile.
// useCount!=0: effective M = g_count (row tiles beyond it early-exit).
// epi==0: C = acc.   epi==2: out[g_selidx[row]*H_ + col] += acc  (FFN down scatter-add)
__global__ __launch_bounds__(256, 2) void gemm_kernel(
    const float* __restrict__ A, const float* __restrict__ B, float* __restrict__ C,
    int M, int N, int K, int useCount, int epi, float* __restrict__ outp)
{
    int effM = useCount ? g_count : M;
    int rowBase = blockIdx.y * 128;
    if (rowBase >= effM) return;
    int colBase = blockIdx.x * 128;

    __shared__ float As[8][132];   // padded: conflict-free transposed stores
    __shared__ float Bs[8][128];

    int tid = threadIdx.x;
    int tx = tid & 15;
    int ty = tid >> 4;

    float acc[8][8];
    #pragma unroll
    for (int i = 0; i < 8; i++)
        #pragma unroll
        for (int j = 0; j < 8; j++) acc[i][j] = 0.f;

    int aRow = tid >> 1;          // 0..127
    int aCol = (tid & 1) << 2;    // 0 or 4
    int bRow = tid >> 5;          // 0..7
    int bCol = (tid & 31) << 2;   // 0..124

    const float* Ap = A + (size_t)(rowBase + aRow) * K + aCol;
    const float* Bp = B + (size_t)bRow * N + colBase + bCol;
    bool aValid = (rowBase + aRow) < effM;

    for (int k0 = 0; k0 < K; k0 += 8) {
        float4 av = aValid ? *(const float4*)Ap : make_float4(0.f,0.f,0.f,0.f);
        float4 bv = *(const float4*)Bp;
        As[aCol+0][aRow] = av.x; As[aCol+1][aRow] = av.y;
        As[aCol+2][aRow] = av.z; As[aCol+3][aRow] = av.w;
        *(float4*)(&Bs[bRow][bCol]) = bv;
        __syncthreads();
        #pragma unroll
        for (int kk = 0; kk < 8; kk++) {
            float a[8], b[8];
            *(float4*)&a[0] = *(const float4*)&As[kk][ty*8];
            *(float4*)&a[4] = *(const float4*)&As[kk][ty*8+4];
            *(float4*)&b[0] = *(const float4*)&Bs[kk][tx*8];
            *(float4*)&b[4] = *(const float4*)&Bs[kk][tx*8+4];
            #pragma unroll
            for (int i = 0; i < 8; i++)
                #pragma unroll
                for (int j = 0; j < 8; j++)
                    acc[i][j] += a[i] * b[j];
        }
        __syncthreads();
        Ap += 8;
        Bp += (size_t)8 * N;
    }

    if (epi == 0) {
        #pragma unroll
        for (int i = 0; i < 8; i++) {
            int row = rowBase + ty*8 + i;
            if (row < effM) {
                float* cp = C + (size_t)row * N + colBase + tx*8;
                *(float4*)cp     = make_float4(acc[i][0], acc[i][1], acc[i][2], acc[i][3]);
                *(float4*)(cp+4) = make_float4(acc[i][4], acc[i][5], acc[i][6], acc[i][7]);
            }
        }
    } else {
        #pragma unroll
        for (int i = 0; i < 8; i++) {
            int row = rowBase + ty*8 + i;
            if (row < effM) {
                int t = g_selidx[row];
                float* op = outp + (size_t)t * H_ + colBase + tx*8;
                float4 v0 = *(float4*)op;
                float4 v1 = *(float4*)(op+4);
                v0.x += acc[i][0]; v0.y += acc[i][1]; v0.z += acc[i][2]; v0.w += acc[i][3];
                v1.x += acc[i][4]; v1.y += acc[i][5]; v1.z += acc[i][6]; v1.w += acc[i][7];
                *(float4*)op     = v0;
                *(float4*)(op+4) = v1;
            }
        }
    }
}

// ---------------- launch ----------------
extern "C" void kernel_launch(void* const* d_in, const int* in_sizes, int n_in,
                              void* d_out, int out_size) {
    const float* x   = (const float*)d_in[0];
    const float* wr  = (const float*)d_in[1];
    const float* br  = (const float*)d_in[2];
    // d_in[3] = Wq, d_in[4] = Wk: provably unused (softmax over singleton axis == 1)
    const float* Wv  = (const float*)d_in[5];
    const float* Wo  = (const float*)d_in[6];
    const float* wg  = (const float*)d_in[7];
    const float* wu  = (const float*)d_in[8];
    const float* wd  = (const float*)d_in[9];
    const float* n1w = (const float*)d_in[10];
    const float* n2w = (const float*)d_in[11];
    float* out = (float*)d_out;

    float *p_bufA, *p_attn, *p_wvwo, *p_gate, *p_up;
    cudaGetSymbolAddress((void**)&p_bufA, g_bufA);
    cudaGetSymbolAddress((void**)&p_attn, g_attn);
    cudaGetSymbolAddress((void**)&p_wvwo, g_wvwo);
    cudaGetSymbolAddress((void**)&p_gate, g_gate);
    cudaGetSymbolAddress((void**)&p_up,   g_up);

    reset_kernel<<<1, 1>>>();
    router_kernel<<<NTOK, 256>>>(x, wr, br);
    thresh_kernel<<<B_, 1024>>>();
    select_kernel<<<NTOK/256, 256>>>();
    copyx_kernel<<<NTOK, 256>>>(x, out);
    gather_kernel<<<NTOK, 256>>>(x, n1w);

    // WvWo = Wv @ Wo  (2048^3, once per launch)
    gemm_kernel<<<dim3(H_/128, H_/128), 256>>>(Wv, Wo, p_wvwo, H_, H_, H_, 0, 0, nullptr);
    // attn = n1c @ WvWo   (compact rows)
    gemm_kernel<<<dim3(H_/128, NTOK/128), 256>>>(p_bufA, p_wvwo, p_attn, NTOK, H_, H_, 1, 0, nullptr);
    // res + rmsnorm2
    res_kernel<<<NTOK, 256>>>(x, n2w, out);
    // gate / up projections
    gemm_kernel<<<dim3(DFF_/128, NTOK/128), 256>>>(p_bufA, wg, p_gate, NTOK, DFF_, H_, 1, 0, nullptr);
    gemm_kernel<<<dim3(DFF_/128, NTOK/128), 256>>>(p_bufA, wu, p_up,   NTOK, DFF_, H_, 1, 0, nullptr);
    // h = silu(gate) * up
    swiglu_kernel<<<(NTOK * (DFF_/4)) / 256, 256>>>();
    // out[selected] += h @ w_down
    gemm_kernel<<<dim3(H_/128, NTOK/128), 256>>>(p_gate, wd, nullptr, NTOK, H_, DFF_, 1, 2, out);
}

// round 3
// speedup vs baseline: 5.5810x; 5.5810x over previous
#include <cuda_runtime.h>
#include <cstdint>
#include <math.h>

// Problem constants
#define B_    4
#define S_    4096
#define H_    2048
#define DFF_  8192
#define NTOK  (B_*S_)      // 16384 tokens
#define KCAP  (S_/2)       // top-k k = 2048
#define EPSF  1e-5f

// ---------------- static device scratch (allocation-free rule) ----------------
__device__ float g_weights[NTOK];
__device__ float g_rstd1[NTOK];
__device__ float g_thresh[B_];
__device__ int   g_selidx[NTOK];
__device__ int   g_count;

__device__ float g_bufA[(size_t)NTOK * H_];     // n1 compact, then n2 compact (tf32-rounded)
__device__ float g_attn[(size_t)NTOK * H_];     // attn_out compact
__device__ float g_wvwo[(size_t)H_ * H_];       // Pt[m][k] = (Wv@Wo)[k][m], tf32
__device__ float g_gate[(size_t)NTOK * DFF_];   // gate proj, then h = silu(g)*u (tf32)
__device__ float g_up  [(size_t)NTOK * DFF_];   // up proj
__device__ float g_woT [(size_t)H_ * H_];       // Wo^T  (tf32)
__device__ float g_wvR [(size_t)H_ * H_];       // Wv rounded (tf32)
__device__ float g_wgT [(size_t)H_ * DFF_];     // w_gate^T [DFF,H] (tf32)
__device__ float g_wuT [(size_t)H_ * DFF_];     // w_up^T   [DFF,H] (tf32)
__device__ float g_wdT [(size_t)H_ * DFF_];     // w_down^T [H,DFF] (tf32)

// ---------------- helpers ----------------
__device__ __forceinline__ float to_tf32(float x) {
    float y;
    asm("cvt.rna.tf32.f32 %0, %1;" : "=f"(y) : "f"(x));
    return y;
}

__device__ __forceinline__ uint32_t smem_u32(const void* p) {
    uint32_t a;
    asm("{ .reg .u64 t; cvta.to.shared.u64 t, %1; cvt.u32.u64 %0, t; }" : "=r"(a) : "l"(p));
    return a;
}

__device__ __forceinline__ void cp16(uint32_t dst, const void* src) {
    asm volatile("cp.async.cg.shared.global [%0], [%1], 16;" :: "r"(dst), "l"(src));
}

__device__ __forceinline__ void mma_tf32(float* d, const uint32_t* a, const uint32_t* b) {
    asm volatile(
        "mma.sync.aligned.m16n8k8.row.col.f32.tf32.tf32.f32 "
        "{%0,%1,%2,%3}, {%4,%5,%6,%7}, {%8,%9}, {%0,%1,%2,%3};"
        : "+f"(d[0]), "+f"(d[1]), "+f"(d[2]), "+f"(d[3])
        : "r"(a[0]), "r"(a[1]), "r"(a[2]), "r"(a[3]), "r"(b[0]), "r"(b[1]));
}

// ---------------- small kernels ----------------

__global__ void reset_kernel() { g_count = 0; }

__global__ void router_kernel(const float* __restrict__ x,
                              const float* __restrict__ wr,
                              const float* __restrict__ br) {
    int t = blockIdx.x;
    const float4* x4 = (const float4*)(x + (size_t)t * H_);
    const float4* w4 = (const float4*)wr;
    float dot = 0.f, ss = 0.f;
    for (int i = threadIdx.x; i < H_/4; i += blockDim.x) {
        float4 xv = x4[i], wv = w4[i];
        dot += xv.x*wv.x + xv.y*wv.y + xv.z*wv.z + xv.w*wv.w;
        ss  += xv.x*xv.x + xv.y*xv.y + xv.z*xv.z + xv.w*xv.w;
    }
    __shared__ float sd[256], sq[256];
    sd[threadIdx.x] = dot; sq[threadIdx.x] = ss;
    __syncthreads();
    for (int s = 128; s > 0; s >>= 1) {
        if (threadIdx.x < s) { sd[threadIdx.x] += sd[threadIdx.x+s]; sq[threadIdx.x] += sq[threadIdx.x+s]; }
        __syncthreads();
    }
    if (threadIdx.x == 0) {
        float l = sd[0] + br[0];
        g_weights[t] = 1.f / (1.f + expf(-l));
        g_rstd1[t]   = rsqrtf(sq[0] / (float)H_ + EPSF);
    }
}

__global__ void thresh_kernel() {
    __shared__ float s[S_];
    int b = blockIdx.x;
    for (int i = threadIdx.x; i < S_; i += blockDim.x) s[i] = g_weights[(size_t)b * S_ + i];
    __syncthreads();
    for (int k = 2; k <= S_; k <<= 1) {
        for (int j = k >> 1; j > 0; j >>= 1) {
            for (int i = threadIdx.x; i < S_; i += blockDim.x) {
                int ixj = i ^ j;
                if (ixj > i) {
                    float a = s[i], c = s[ixj];
                    bool desc = ((i & k) == 0);
                    if (desc ? (a < c) : (a > c)) { s[i] = c; s[ixj] = a; }
                }
            }
            __syncthreads();
        }
    }
    if (threadIdx.x == 0) g_thresh[b] = s[KCAP - 1];
}

__global__ void select_kernel() {
    int t = blockIdx.x * blockDim.x + threadIdx.x;
    if (t >= NTOK) return;
    if (g_weights[t] >= g_thresh[t / S_]) {
        int p = atomicAdd(&g_count, 1);
        g_selidx[p] = t;
    }
}

__global__ void copyx_kernel(const float* __restrict__ x, float* __restrict__ out) {
    int t = blockIdx.x;
    if (g_weights[t] >= g_thresh[t / S_]) return;
    const float4* x4 = (const float4*)(x + (size_t)t * H_);
    float4* o4 = (float4*)(out + (size_t)t * H_);
    for (int i = threadIdx.x; i < H_/4; i += blockDim.x) o4[i] = x4[i];
}

// n1 = tf32(rmsnorm(x)*norm1_w), compact
__global__ void gather_kernel(const float* __restrict__ x, const float* __restrict__ n1w) {
    int r = blockIdx.x;
    if (r >= g_count) return;
    int t = g_selidx[r];
    float rs = g_rstd1[t];
    const float4* x4 = (const float4*)(x + (size_t)t * H_);
    const float4* w4 = (const float4*)n1w;
    float4* o4 = (float4*)(g_bufA + (size_t)r * H_);
    for (int i = threadIdx.x; i < H_/4; i += blockDim.x) {
        float4 xv = x4[i], wv = w4[i];
        o4[i] = make_float4(to_tf32(xv.x*rs*wv.x), to_tf32(xv.y*rs*wv.y),
                            to_tf32(xv.z*rs*wv.z), to_tf32(xv.w*rs*wv.w));
    }
}

// res = x + attn; out[token]=res; bufA = tf32(rmsnorm(res)*norm2_w)
__global__ void res_kernel(const float* __restrict__ x, const float* __restrict__ n2w,
                           float* __restrict__ out) {
    int r = blockIdx.x;
    if (r >= g_count) return;
    int t = g_selidx[r];
    __shared__ float sres[H_];
    __shared__ float red[256];
    const float4* x4 = (const float4*)(x + (size_t)t * H_);
    const float4* a4 = (const float4*)(g_attn + (size_t)r * H_);
    float ss = 0.f;
    for (int i = threadIdx.x; i < H_/4; i += blockDim.x) {
        float4 xv = x4[i], av = a4[i];
        float4 rv = make_float4(xv.x+av.x, xv.y+av.y, xv.z+av.z, xv.w+av.w);
        ((float4*)sres)[i] = rv;
        ss += rv.x*rv.x + rv.y*rv.y + rv.z*rv.z + rv.w*rv.w;
    }
    red[threadIdx.x] = ss;
    __syncthreads();
    for (int s = 128; s > 0; s >>= 1) {
        if (threadIdx.x < s) red[threadIdx.x] += red[threadIdx.x+s];
        __syncthreads();
    }
    float rstd = rsqrtf(red[0] / (float)H_ + EPSF);
    float4* o4 = (float4*)(out + (size_t)t * H_);
    float4* n4 = (float4*)(g_bufA + (size_t)r * H_);
    const float4* w4 = (const float4*)n2w;
    for (int i = threadIdx.x; i < H_/4; i += blockDim.x) {
        float4 rv = ((float4*)sres)[i];
        float4 wv = w4[i];
        o4[i] = rv;
        n4[i] = make_float4(to_tf32(rv.x*rstd*wv.x), to_tf32(rv.y*rstd*wv.y),
                            to_tf32(rv.z*rstd*wv.z), to_tf32(rv.w*rstd*wv.w));
    }
}

// h = tf32(silu(gate) * up) in place into g_gate
__global__ void swiglu_kernel() {
    size_t n4 = (size_t)g_count * (DFF_/4);
    size_t i = (size_t)blockIdx.x * blockDim.x + threadIdx.x;
    if (i >= n4) return;
    float4 g = ((const float4*)g_gate)[i];
    float4 u = ((const float4*)g_up)[i];
    float4 h;
    h.x = to_tf32(g.x / (1.f + expf(-g.x)) * u.x);
    h.y = to_tf32(g.y / (1.f + expf(-g.y)) * u.y);
    h.z = to_tf32(g.z / (1.f + expf(-g.z)) * u.z);
    h.w = to_tf32(g.w / (1.f + expf(-g.w)) * u.w);
    ((float4*)g_gate)[i] = h;
}

// tiled transpose with tf32 rounding: dst[c][r] = tf32(src[r][c])
__global__ void transpose_kernel(const float* __restrict__ src, float* __restrict__ dst,
                                 int R, int C) {
    __shared__ float tile[32][33];
    int c0 = blockIdx.x * 32, r0 = blockIdx.y * 32;
    int tx = threadIdx.x, ty = threadIdx.y;
    #pragma unroll
    for (int j = 0; j < 4; j++) {
        int r = r0 + ty + j*8;
        tile[ty + j*8][tx] = to_tf32(src[(size_t)r * C + c0 + tx]);
    }
    __syncthreads();
    #pragma unroll
    for (int j = 0; j < 4; j++) {
        int c = c0 + ty + j*8;
        dst[(size_t)c * R + r0 + tx] = tile[tx][ty + j*8];
    }
}

__global__ void roundcopy_kernel(const float* __restrict__ src, float* __restrict__ dst, size_t n4) {
    size_t i = (size_t)blockIdx.x * blockDim.x + threadIdx.x;
    if (i >= n4) return;
    float4 v = ((const float4*)src)[i];
    ((float4*)dst)[i] = make_float4(to_tf32(v.x), to_tf32(v.y), to_tf32(v.z), to_tf32(v.w));
}

// ---------------- tf32 mma.sync GEMM ----------------
// C[M,N] = A[M,K] * B[N,K]^T  (both operands K-major row-major).
// CTA 128x128, K_TILE=32, 4-stage cp.async pipeline, 8 warps, warp tile 64x32.
// epi: 0 = store fp32, 1 = store tf32-rounded, 2 = scatter-add out[g_selidx[row]*H_+col]
#define STAGES   4
#define KT_F     32                 // floats per K-tile
#define ROWSTR   36                 // padded row stride in floats (32+4)
#define TILE_F   (128 * ROWSTR)     // floats per stage per operand
#define GSMEM_BYTES (2 * STAGES * TILE_F * 4)   // 147456

__global__ __launch_bounds__(256, 1) void gemm_mma(
    const float* __restrict__ A, const float* __restrict__ B, float* __restrict__ C,
    int M, int N, int K, int useCount, int epi, float* __restrict__ outp)
{
    int effM = useCount ? g_count : M;
    int rowBase = blockIdx.y * 128;
    if (rowBase >= effM) return;
    int colBase = blockIdx.x * 128;

    extern __shared__ float smem[];
    float* As = smem;                       // [STAGES][128][ROWSTR]
    float* Bs = smem + STAGES * TILE_F;
    uint32_t asBase = smem_u32(As);
    uint32_t bsBase = smem_u32(Bs);

    int tid  = threadIdx.x;
    int wid  = tid >> 5;
    int lane = tid & 31;
    int grp  = lane >> 2;      // 0..7
    int tig  = lane & 3;       // 0..3
    int wm   = (wid & 1) * 64; // warp row offset
    int wn   = (wid >> 1) * 32;// warp col offset

    const float* Ag = A + (size_t)rowBase * K;
    const float* Bg = B + (size_t)colBase * K;
    int KT = K >> 5;

    // per-thread load slots: 4 float4 per operand per tile
    int lrow[4], lcol[4];
    #pragma unroll
    for (int i = 0; i < 4; i++) {
        int c = tid + (i << 8);       // 0..1023
        lrow[i] = c >> 3;             // 0..127
        lcol[i] = (c & 7) << 2;       // float offset (0,4,...,28)
    }

    auto load_tile = [&](int s, int kt) {
        int kb = kt << 5;
        uint32_t as = asBase + (uint32_t)s * TILE_F * 4;
        uint32_t bs = bsBase + (uint32_t)s * TILE_F * 4;
        #pragma unroll
        for (int i = 0; i < 4; i++) {
            uint32_t soff = (uint32_t)(lrow[i] * ROWSTR + lcol[i]) * 4;
            cp16(as + soff, Ag + (size_t)lrow[i] * K + kb + lcol[i]);
            cp16(bs + soff, Bg + (size_t)lrow[i] * K + kb + lcol[i]);
        }
        asm volatile("cp.async.commit_group;" ::: "memory");
    };

    #pragma unroll
    for (int p = 0; p < STAGES - 1; p++) load_tile(p, p);

    float acc[4][4][4];
    #pragma unroll
    for (int i = 0; i < 4; i++)
        #pragma unroll
        for (int j = 0; j < 4; j++)
            #pragma unroll
            for (int q = 0; q < 4; q++) acc[i][j][q] = 0.f;

    for (int kt = 0; kt < KT; kt++) {
        int s = kt & (STAGES - 1);
        int remain = KT - 1 - kt;
        if (remain >= 2)      asm volatile("cp.async.wait_group 2;" ::: "memory");
        else if (remain == 1) asm volatile("cp.async.wait_group 1;" ::: "memory");
        else                  asm volatile("cp.async.wait_group 0;" ::: "memory");
        __syncthreads();

        int nt = kt + STAGES - 1;
        if (nt < KT) load_tile(nt & (STAGES - 1), nt);

        const float* Asl = As + s * TILE_F;
        const float* Bsl = Bs + s * TILE_F;

        #pragma unroll
        for (int ks = 0; ks < 4; ks++) {
            int kc = ks * 8 + tig;
            uint32_t afr[4][4], bfr[4][2];
            #pragma unroll
            for (int i = 0; i < 4; i++) {
                int ar = wm + i * 16 + grp;
                afr[i][0] = __float_as_uint(Asl[ar * ROWSTR + kc]);
                afr[i][1] = __float_as_uint(Asl[(ar + 8) * ROWSTR + kc]);
                afr[i][2] = __float_as_uint(Asl[ar * ROWSTR + kc + 4]);
                afr[i][3] = __float_as_uint(Asl[(ar + 8) * ROWSTR + kc + 4]);
            }
            #pragma unroll
            for (int j = 0; j < 4; j++) {
                int bn = wn + j * 8 + grp;
                bfr[j][0] = __float_as_uint(Bsl[bn * ROWSTR + kc]);
                bfr[j][1] = __float_as_uint(Bsl[bn * ROWSTR + kc + 4]);
            }
            #pragma unroll
            for (int i = 0; i < 4; i++)
                #pragma unroll
                for (int j = 0; j < 4; j++)
                    mma_tf32(acc[i][j], afr[i], bfr[j]);
        }
    }

    // Epilogue. c0:(grp,tig*2) c1:(grp,tig*2+1) c2:(grp+8,tig*2) c3:(grp+8,tig*2+1)
    #pragma unroll
    for (int i = 0; i < 4; i++) {
        int r0 = rowBase + wm + i * 16 + grp;
        int r1 = r0 + 8;
        #pragma unroll
        for (int j = 0; j < 4; j++) {
            int col = colBase + wn + j * 8 + tig * 2;
            if (epi == 2) {
                if (r0 < effM) {
                    float* op = outp + (size_t)g_selidx[r0] * H_ + col;
                    op[0] += acc[i][j][0]; op[1] += acc[i][j][1];
                }
                if (r1 < effM) {
                    float* op = outp + (size_t)g_selidx[r1] * H_ + col;
                    op[0] += acc[i][j][2]; op[1] += acc[i][j][3];
                }
            } else if (epi == 1) {
                if (r0 < effM) {
                    float* cp = C + (size_t)r0 * N + col;
                    cp[0] = to_tf32(acc[i][j][0]); cp[1] = to_tf32(acc[i][j][1]);
                }
                if (r1 < effM) {
                    float* cp = C + (size_t)r1 * N + col;
                    cp[0] = to_tf32(acc[i][j][2]); cp[1] = to_tf32(acc[i][j][3]);
                }
            } else {
                if (r0 < effM) {
                    *(float2*)(C + (size_t)r0 * N + col) = make_float2(acc[i][j][0], acc[i][j][1]);
                }
                if (r1 < effM) {
                    *(float2*)(C + (size_t)r1 * N + col) = make_float2(acc[i][j][2], acc[i][j][3]);
                }
            }
        }
    }
}

// ---------------- launch ----------------
extern "C" void kernel_launch(void* const* d_in, const int* in_sizes, int n_in,
                              void* d_out, int out_size) {
    const float* x   = (const float*)d_in[0];
    const float* wr  = (const float*)d_in[1];
    const float* br  = (const float*)d_in[2];
    // d_in[3]=Wq, d_in[4]=Wk: unused (softmax over singleton axis == 1 -> ctx = v)
    const float* Wv  = (const float*)d_in[5];
    const float* Wo  = (const float*)d_in[6];
    const float* wg  = (const float*)d_in[7];
    const float* wu  = (const float*)d_in[8];
    const float* wd  = (const float*)d_in[9];
    const float* n1w = (const float*)d_in[10];
    const float* n2w = (const float*)d_in[11];
    float* out = (float*)d_out;

    cudaFuncSetAttribute(gemm_mma, cudaFuncAttributeMaxDynamicSharedMemorySize, GSMEM_BYTES);

    float *p_bufA, *p_attn, *p_wvwo, *p_gate, *p_up, *p_woT, *p_wvR, *p_wgT, *p_wuT, *p_wdT;
    cudaGetSymbolAddress((void**)&p_bufA, g_bufA);
    cudaGetSymbolAddress((void**)&p_attn, g_attn);
    cudaGetSymbolAddress((void**)&p_wvwo, g_wvwo);
    cudaGetSymbolAddress((void**)&p_gate, g_gate);
    cudaGetSymbolAddress((void**)&p_up,   g_up);
    cudaGetSymbolAddress((void**)&p_woT,  g_woT);
    cudaGetSymbolAddress((void**)&p_wvR,  g_wvR);
    cudaGetSymbolAddress((void**)&p_wgT,  g_wgT);
    cudaGetSymbolAddress((void**)&p_wuT,  g_wuT);
    cudaGetSymbolAddress((void**)&p_wdT,  g_wdT);

    reset_kernel<<<1, 1>>>();
    router_kernel<<<NTOK, 256>>>(x, wr, br);
    thresh_kernel<<<B_, 1024>>>();
    select_kernel<<<NTOK/256, 256>>>();
    copyx_kernel<<<NTOK, 256>>>(x, out);
    gather_kernel<<<NTOK, 256>>>(x, n1w);

    // weight prep (tf32-rounded, K-major B operands)
    dim3 tb(32, 8);
    transpose_kernel<<<dim3(H_/32,   H_/32),  tb>>>(Wo, p_woT, H_, H_);     // WoT [H,H]
    transpose_kernel<<<dim3(DFF_/32, H_/32),  tb>>>(wg, p_wgT, H_, DFF_);   // wgT [DFF,H]
    transpose_kernel<<<dim3(DFF_/32, H_/32),  tb>>>(wu, p_wuT, H_, DFF_);   // wuT [DFF,H]
    transpose_kernel<<<dim3(H_/32,   DFF_/32),tb>>>(wd, p_wdT, DFF_, H_);   // wdT [H,DFF]
    roundcopy_kernel<<<(H_*H_/4)/256, 256>>>(Wv, p_wvR, (size_t)H_*H_/4);

    // Pt = WoT x WvR^T : Pt[m][n] = (Wv@Wo)[n][m], tf32-rounded store
    gemm_mma<<<dim3(H_/128, H_/128), 256, GSMEM_BYTES>>>(p_woT, p_wvR, p_wvwo, H_, H_, H_, 0, 1, nullptr);
    // attn = n1c x Pt^T
    gemm_mma<<<dim3(H_/128, NTOK/128), 256, GSMEM_BYTES>>>(p_bufA, p_wvwo, p_attn, NTOK, H_, H_, 1, 0, nullptr);
    // res + rmsnorm2
    res_kernel<<<NTOK, 256>>>(x, n2w, out);
    // gate / up projections
    gemm_mma<<<dim3(DFF_/128, NTOK/128), 256, GSMEM_BYTES>>>(p_bufA, p_wgT, p_gate, NTOK, DFF_, H_, 1, 0, nullptr);
    gemm_mma<<<dim3(DFF_/128, NTOK/128), 256, GSMEM_BYTES>>>(p_bufA, p_wuT, p_up,   NTOK, DFF_, H_, 1, 0, nullptr);
    // h = tf32(silu(gate) * up)
    swiglu_kernel<<<(NTOK * (DFF_/4)) / 256, 256>>>();
    // out[selected] += h x wdT^T
    gemm_mma<<<dim3(H_/128, NTOK/128), 256, GSMEM_BYTES>>>(p_gate, p_wdT, nullptr, NTOK, H_, DFF_, 1, 2, out);
}

// round 4
// speedup vs baseline: 10.9454x; 1.9612x over previous
#include <cuda_runtime.h>
#include <cuda_fp16.h>
#include <cstdint>
#include <math.h>

// Problem constants
#define B_    4
#define S_    4096
#define H_    2048
#define DFF_  8192
#define NTOK  (B_*S_)      // 16384 tokens
#define KCAP  (S_/2)       // top-k k = 2048
#define EPSF  1e-5f

// ---------------- static device scratch (allocation-free rule) ----------------
__device__ float  g_weights[NTOK];
__device__ float  g_rstd1[NTOK];
__device__ float  g_thresh[B_];
__device__ int    g_selidx[NTOK];
__device__ int    g_count;

__device__ __half g_bufA[(size_t)NTOK * H_];    // n1 compact, then n2 compact (fp16)
__device__ float  g_attn[(size_t)NTOK * H_];    // attn_out compact (fp32)
__device__ __half g_PtH [(size_t)H_ * H_];      // Pt[m][k] = (Wv@Wo)[k][m] (fp16)
__device__ __half g_gateH[(size_t)NTOK * DFF_]; // gate proj (fp16)
__device__ __half g_upH  [(size_t)NTOK * DFF_]; // up proj (fp16)
__device__ __half g_hbuf [(size_t)NTOK * DFF_]; // h = silu(g)*u (fp16)
__device__ __half g_woT [(size_t)H_ * H_];      // Wo^T (fp16)
__device__ __half g_wvH [(size_t)H_ * H_];      // Wv (fp16)
__device__ __half g_wgT [(size_t)H_ * DFF_];    // w_gate^T [DFF,H] (fp16)
__device__ __half g_wuT [(size_t)H_ * DFF_];    // w_up^T   [DFF,H] (fp16)
__device__ __half g_wdT [(size_t)H_ * DFF_];    // w_down^T [H,DFF] (fp16)

// ---------------- helpers ----------------
__device__ __forceinline__ uint32_t smem_u32(const void* p) {
    uint32_t a;
    asm("{ .reg .u64 t; cvta.to.shared.u64 t, %1; cvt.u32.u64 %0, t; }" : "=r"(a) : "l"(p));
    return a;
}

__device__ __forceinline__ void cp16(uint32_t dst, const void* src) {
    asm volatile("cp.async.cg.shared.global [%0], [%1], 16;" :: "r"(dst), "l"(src));
}

__device__ __forceinline__ void ldsm4(uint32_t* r, uint32_t addr) {
    asm volatile("ldmatrix.sync.aligned.m8n8.x4.shared.b16 {%0,%1,%2,%3}, [%4];"
        : "=r"(r[0]), "=r"(r[1]), "=r"(r[2]), "=r"(r[3]) : "r"(addr));
}

__device__ __forceinline__ void mma_f16(float* d, const uint32_t* a, const uint32_t* b) {
    asm volatile(
        "mma.sync.aligned.m16n8k16.row.col.f32.f16.f16.f32 "
        "{%0,%1,%2,%3}, {%4,%5,%6,%7}, {%8,%9}, {%0,%1,%2,%3};"
        : "+f"(d[0]), "+f"(d[1]), "+f"(d[2]), "+f"(d[3])
        : "r"(a[0]), "r"(a[1]), "r"(a[2]), "r"(a[3]), "r"(b[0]), "r"(b[1]));
}

// ---------------- small kernels ----------------

__global__ void reset_kernel() { g_count = 0; }

__global__ void router_kernel(const float* __restrict__ x,
                              const float* __restrict__ wr,
                              const float* __restrict__ br) {
    int t = blockIdx.x;
    const float4* x4 = (const float4*)(x + (size_t)t * H_);
    const float4* w4 = (const float4*)wr;
    float dot = 0.f, ss = 0.f;
    for (int i = threadIdx.x; i < H_/4; i += blockDim.x) {
        float4 xv = x4[i], wv = w4[i];
        dot += xv.x*wv.x + xv.y*wv.y + xv.z*wv.z + xv.w*wv.w;
        ss  += xv.x*xv.x + xv.y*xv.y + xv.z*xv.z + xv.w*xv.w;
    }
    __shared__ float sd[256], sq[256];
    sd[threadIdx.x] = dot; sq[threadIdx.x] = ss;
    __syncthreads();
    for (int s = 128; s > 0; s >>= 1) {
        if (threadIdx.x < s) { sd[threadIdx.x] += sd[threadIdx.x+s]; sq[threadIdx.x] += sq[threadIdx.x+s]; }
        __syncthreads();
    }
    if (threadIdx.x == 0) {
        float l = sd[0] + br[0];
        g_weights[t] = 1.f / (1.f + expf(-l));
        g_rstd1[t]   = rsqrtf(sq[0] / (float)H_ + EPSF);
    }
}

__global__ void thresh_kernel() {
    __shared__ float s[S_];
    int b = blockIdx.x;
    for (int i = threadIdx.x; i < S_; i += blockDim.x) s[i] = g_weights[(size_t)b * S_ + i];
    __syncthreads();
    for (int k = 2; k <= S_; k <<= 1) {
        for (int j = k >> 1; j > 0; j >>= 1) {
            for (int i = threadIdx.x; i < S_; i += blockDim.x) {
                int ixj = i ^ j;
                if (ixj > i) {
                    float a = s[i], c = s[ixj];
                    bool desc = ((i & k) == 0);
                    if (desc ? (a < c) : (a > c)) { s[i] = c; s[ixj] = a; }
                }
            }
            __syncthreads();
        }
    }
    if (threadIdx.x == 0) g_thresh[b] = s[KCAP - 1];
}

__global__ void select_kernel() {
    int t = blockIdx.x * blockDim.x + threadIdx.x;
    if (t >= NTOK) return;
    if (g_weights[t] >= g_thresh[t / S_]) {
        int p = atomicAdd(&g_count, 1);
        g_selidx[p] = t;
    }
}

__global__ void copyx_kernel(const float* __restrict__ x, float* __restrict__ out) {
    int t = blockIdx.x;
    if (g_weights[t] >= g_thresh[t / S_]) return;
    const float4* x4 = (const float4*)(x + (size_t)t * H_);
    float4* o4 = (float4*)(out + (size_t)t * H_);
    for (int i = threadIdx.x; i < H_/4; i += blockDim.x) o4[i] = x4[i];
}

// n1 = fp16(rmsnorm(x)*norm1_w), compact
__global__ void gather_kernel(const float* __restrict__ x, const float* __restrict__ n1w) {
    int r = blockIdx.x;
    if (r >= g_count) return;
    int t = g_selidx[r];
    float rs = g_rstd1[t];
    const float4* x4 = (const float4*)(x + (size_t)t * H_);
    const float4* w4 = (const float4*)n1w;
    __half2* o2 = (__half2*)(g_bufA + (size_t)r * H_);
    for (int i = threadIdx.x; i < H_/4; i += blockDim.x) {
        float4 xv = x4[i], wv = w4[i];
        o2[2*i]   = __floats2half2_rn(xv.x*rs*wv.x, xv.y*rs*wv.y);
        o2[2*i+1] = __floats2half2_rn(xv.z*rs*wv.z, xv.w*rs*wv.w);
    }
}

// res = x + attn; out[token]=res; bufA = fp16(rmsnorm(res)*norm2_w)
__global__ void res_kernel(const float* __restrict__ x, const float* __restrict__ n2w,
                           float* __restrict__ out) {
    int r = blockIdx.x;
    if (r >= g_count) return;
    int t = g_selidx[r];
    __shared__ float sres[H_];
    __shared__ float red[256];
    const float4* x4 = (const float4*)(x + (size_t)t * H_);
    const float4* a4 = (const float4*)(g_attn + (size_t)r * H_);
    float ss = 0.f;
    for (int i = threadIdx.x; i < H_/4; i += blockDim.x) {
        float4 xv = x4[i], av = a4[i];
        float4 rv = make_float4(xv.x+av.x, xv.y+av.y, xv.z+av.z, xv.w+av.w);
        ((float4*)sres)[i] = rv;
        ss += rv.x*rv.x + rv.y*rv.y + rv.z*rv.z + rv.w*rv.w;
    }
    red[threadIdx.x] = ss;
    __syncthreads();
    for (int s = 128; s > 0; s >>= 1) {
        if (threadIdx.x < s) red[threadIdx.x] += red[threadIdx.x+s];
        __syncthreads();
    }
    float rstd = rsqrtf(red[0] / (float)H_ + EPSF);
    float4* o4 = (float4*)(out + (size_t)t * H_);
    __half2* n2b = (__half2*)(g_bufA + (size_t)r * H_);
    const float4* w4 = (const float4*)n2w;
    for (int i = threadIdx.x; i < H_/4; i += blockDim.x) {
        float4 rv = ((float4*)sres)[i];
        float4 wv = w4[i];
        o4[i] = rv;
        n2b[2*i]   = __floats2half2_rn(rv.x*rstd*wv.x, rv.y*rstd*wv.y);
        n2b[2*i+1] = __floats2half2_rn(rv.z*rstd*wv.z, rv.w*rstd*wv.w);
    }
}

// h = fp16(silu(gate) * up) into g_hbuf
__global__ void swiglu_kernel() {
    size_t n2 = (size_t)g_count * (DFF_/2);
    size_t i = (size_t)blockIdx.x * blockDim.x + threadIdx.x;
    if (i >= n2) return;
    float2 g = __half22float2(((const __half2*)g_gateH)[i]);
    float2 u = __half22float2(((const __half2*)g_upH)[i]);
    float hx = g.x / (1.f + expf(-g.x)) * u.x;
    float hy = g.y / (1.f + expf(-g.y)) * u.y;
    ((__half2*)g_hbuf)[i] = __floats2half2_rn(hx, hy);
}

// tiled transpose fp32 -> fp16: dst[c][r] = half(src[r][c])
__global__ void transposeH_kernel(const float* __restrict__ src, __half* __restrict__ dst,
                                  int R, int C) {
    __shared__ float tile[32][33];
    int c0 = blockIdx.x * 32, r0 = blockIdx.y * 32;
    int tx = threadIdx.x, ty = threadIdx.y;
    #pragma unroll
    for (int j = 0; j < 4; j++) {
        int r = r0 + ty + j*8;
        tile[ty + j*8][tx] = src[(size_t)r * C + c0 + tx];
    }
    __syncthreads();
    #pragma unroll
    for (int j = 0; j < 4; j++) {
        int c = c0 + ty + j*8;
        dst[(size_t)c * R + r0 + tx] = __float2half_rn(tile[tx][ty + j*8]);
    }
}

// fp32 -> fp16 copy
__global__ void h_copy_kernel(const float* __restrict__ src, __half* __restrict__ dst, size_t n4) {
    size_t i = (size_t)blockIdx.x * blockDim.x + threadIdx.x;
    if (i >= n4) return;
    float4 v = ((const float4*)src)[i];
    ((__half2*)dst)[2*i]   = __floats2half2_rn(v.x, v.y);
    ((__half2*)dst)[2*i+1] = __floats2half2_rn(v.z, v.w);
}

// ---------------- fp16 mma.sync GEMM ----------------
// C[M,N] = A[M,K] * B[N,K]^T  (half operands, K-major rows, fp32 accumulate).
// CTA 128x256, 8 warps (warp tile 64x64), K_TILE=64 halves (128B rows),
// 4-stage cp.async pipeline, ldmatrix.x4 fragment loads.
// epi: 0 = store fp32, 1 = store fp16, 2 = scatter-add fp32 out[g_selidx[row]*H_+col]
#define STAGES   4
#define KTH      64                 // halves per K-tile
#define RS       72                 // padded row stride in halves (64+8 -> 144B rows)
#define A_ST     (128 * RS)         // halves per A stage
#define B_ST     (256 * RS)         // halves per B stage
#define GSMEM_BYTES ((A_ST + B_ST) * 2 * STAGES)   // 221184

__global__ __launch_bounds__(256, 1) void gemm_h(
    const __half* __restrict__ A, const __half* __restrict__ B, void* __restrict__ Cv,
    int M, int N, int K, int useCount, int epi, float* __restrict__ outp)
{
    int effM = useCount ? g_count : M;
    int rowBase = blockIdx.y * 128;
    if (rowBase >= effM) return;
    int colBase = blockIdx.x * 256;

    extern __shared__ __half smem[];
    uint32_t asBase = smem_u32(smem);
    uint32_t bsBase = asBase + (uint32_t)STAGES * A_ST * 2;

    int tid  = threadIdx.x;
    int wid  = tid >> 5;
    int lane = tid & 31;
    int grp  = lane >> 2;       // 0..7
    int tig  = lane & 3;        // 0..3
    int wm   = (wid & 1) * 64;  // warp row offset (0/64)
    int wn   = (wid >> 1) * 64; // warp col offset (0/64/128/192)

    const __half* Ag = A + (size_t)rowBase * K;
    const __half* Bg = B + (size_t)colBase * K;
    int KT = K >> 6;            // K / 64

    auto load_tile = [&](int s, int kt) {
        int kb = kt << 6;
        uint32_t as = asBase + (uint32_t)s * A_ST * 2;
        uint32_t bs = bsBase + (uint32_t)s * B_ST * 2;
        #pragma unroll
        for (int i = 0; i < 4; i++) {          // A: 1024 16B-chunks
            int c = tid + (i << 8);
            int row = c >> 3, ch = c & 7;
            cp16(as + (uint32_t)(row * RS + ch * 8) * 2,
                 Ag + (size_t)row * K + kb + ch * 8);
        }
        #pragma unroll
        for (int i = 0; i < 8; i++) {          // B: 2048 16B-chunks
            int c = tid + (i << 8);
            int row = c >> 3, ch = c & 7;
            cp16(bs + (uint32_t)(row * RS + ch * 8) * 2,
                 Bg + (size_t)row * K + kb + ch * 8);
        }
        asm volatile("cp.async.commit_group;" ::: "memory");
    };

    #pragma unroll
    for (int p = 0; p < STAGES - 1; p++) load_tile(p, p);

    float acc[4][8][4];
    #pragma unroll
    for (int i = 0; i < 4; i++)
        #pragma unroll
        for (int j = 0; j < 8; j++)
            #pragma unroll
            for (int q = 0; q < 4; q++) acc[i][j][q] = 0.f;

    // per-lane ldmatrix byte offsets (within a stage)
    int lr = lane & 7;
    uint32_t aOff = (uint32_t)((wm + lr + ((lane >> 3) & 1) * 8) * RS + (lane >> 4) * 8) * 2;
    uint32_t bOff = (uint32_t)((wn + lr + (lane >> 4) * 8) * RS + ((lane >> 3) & 1) * 8) * 2;

    for (int kt = 0; kt < KT; kt++) {
        int s = kt & (STAGES - 1);
        int remain = KT - 1 - kt;
        if (remain >= 2)      asm volatile("cp.async.wait_group 2;" ::: "memory");
        else if (remain == 1) asm volatile("cp.async.wait_group 1;" ::: "memory");
        else                  asm volatile("cp.async.wait_group 0;" ::: "memory");
        __syncthreads();

        int nt = kt + STAGES - 1;
        if (nt < KT) load_tile(nt & (STAGES - 1), nt);

        uint32_t aSt = asBase + (uint32_t)s * A_ST * 2;
        uint32_t bSt = bsBase + (uint32_t)s * B_ST * 2;

        #pragma unroll
        for (int ks = 0; ks < 4; ks++) {       // 4 x k16 per K-tile
            uint32_t afr[4][4], bfr[8][2];
            #pragma unroll
            for (int i = 0; i < 4; i++)
                ldsm4(afr[i], aSt + aOff + (uint32_t)i * (16 * RS * 2) + ks * 32);
            #pragma unroll
            for (int j = 0; j < 4; j++) {
                uint32_t t4[4];
                ldsm4(t4, bSt + bOff + (uint32_t)j * (16 * RS * 2) + ks * 32);
                bfr[2*j][0] = t4[0]; bfr[2*j][1] = t4[1];
                bfr[2*j+1][0] = t4[2]; bfr[2*j+1][1] = t4[3];
            }
            #pragma unroll
            for (int i = 0; i < 4; i++)
                #pragma unroll
                for (int j = 0; j < 8; j++)
                    mma_f16(acc[i][j], afr[i], bfr[j]);
        }
    }

    // Epilogue: acc[i][j]: rows (wm+16i+grp, +8), cols wn + 8j + 2*tig (+1)
    #pragma unroll
    for (int i = 0; i < 4; i++) {
        int r0 = rowBase + wm + i * 16 + grp;
        int r1 = r0 + 8;
        #pragma unroll
        for (int j = 0; j < 8; j++) {
            int col = colBase + wn + j * 8 + tig * 2;
            if (epi == 2) {
                if (r0 < effM) {
                    float* op = outp + (size_t)g_selidx[r0] * H_ + col;
                    op[0] += acc[i][j][0]; op[1] += acc[i][j][1];
                }
                if (r1 < effM) {
                    float* op = outp + (size_t)g_selidx[r1] * H_ + col;
                    op[0] += acc[i][j][2]; op[1] += acc[i][j][3];
                }
            } else if (epi == 1) {
                __half* Ch = (__half*)Cv;
                if (r0 < effM)
                    *(__half2*)(Ch + (size_t)r0 * N + col) = __floats2half2_rn(acc[i][j][0], acc[i][j][1]);
                if (r1 < effM)
                    *(__half2*)(Ch + (size_t)r1 * N + col) = __floats2half2_rn(acc[i][j][2], acc[i][j][3]);
            } else {
                float* Cf = (float*)Cv;
                if (r0 < effM)
                    *(float2*)(Cf + (size_t)r0 * N + col) = make_float2(acc[i][j][0], acc[i][j][1]);
                if (r1 < effM)
                    *(float2*)(Cf + (size_t)r1 * N + col) = make_float2(acc[i][j][2], acc[i][j][3]);
            }
        }
    }
}

// ---------------- launch ----------------
extern "C" void kernel_launch(void* const* d_in, const int* in_sizes, int n_in,
                              void* d_out, int out_size) {
    const float* x   = (const float*)d_in[0];
    const float* wr  = (const float*)d_in[1];
    const float* br  = (const float*)d_in[2];
    // d_in[3]=Wq, d_in[4]=Wk: unused (softmax over singleton axis == 1 -> ctx = v)
    const float* Wv  = (const float*)d_in[5];
    const float* Wo  = (const float*)d_in[6];
    const float* wg  = (const float*)d_in[7];
    const float* wu  = (const float*)d_in[8];
    const float* wd  = (const float*)d_in[9];
    const float* n1w = (const float*)d_in[10];
    const float* n2w = (const float*)d_in[11];
    float* out = (float*)d_out;

    cudaFuncSetAttribute(gemm_h, cudaFuncAttributeMaxDynamicSharedMemorySize, GSMEM_BYTES);

    __half *p_bufA, *p_PtH, *p_gateH, *p_upH, *p_hbuf, *p_woT, *p_wvH, *p_wgT, *p_wuT, *p_wdT;
    float *p_attn;
    cudaGetSymbolAddress((void**)&p_bufA,  g_bufA);
    cudaGetSymbolAddress((void**)&p_attn,  g_attn);
    cudaGetSymbolAddress((void**)&p_PtH,   g_PtH);
    cudaGetSymbolAddress((void**)&p_gateH, g_gateH);
    cudaGetSymbolAddress((void**)&p_upH,   g_upH);
    cudaGetSymbolAddress((void**)&p_hbuf,  g_hbuf);
    cudaGetSymbolAddress((void**)&p_woT,   g_woT);
    cudaGetSymbolAddress((void**)&p_wvH,   g_wvH);
    cudaGetSymbolAddress((void**)&p_wgT,   g_wgT);
    cudaGetSymbolAddress((void**)&p_wuT,   g_wuT);
    cudaGetSymbolAddress((void**)&p_wdT,   g_wdT);

    reset_kernel<<<1, 1>>>();
    router_kernel<<<NTOK, 256>>>(x, wr, br);
    thresh_kernel<<<B_, 1024>>>();
    select_kernel<<<NTOK/256, 256>>>();
    copyx_kernel<<<NTOK, 256>>>(x, out);
    gather_kernel<<<NTOK, 256>>>(x, n1w);

    // weight prep (fp16, K-major B operands)
    dim3 tb(32, 8);
    transposeH_kernel<<<dim3(H_/32,   H_/32),  tb>>>(Wo, p_woT, H_, H_);     // WoT [H,H]
    transposeH_kernel<<<dim3(DFF_/32, H_/32),  tb>>>(wg, p_wgT, H_, DFF_);   // wgT [DFF,H]
    transposeH_kernel<<<dim3(DFF_/32, H_/32),  tb>>>(wu, p_wuT, H_, DFF_);   // wuT [DFF,H]
    transposeH_kernel<<<dim3(H_/32,   DFF_/32),tb>>>(wd, p_wdT, DFF_, H_);   // wdT [H,DFF]
    h_copy_kernel<<<(H_*H_/4)/256, 256>>>(Wv, p_wvH, (size_t)H_*H_/4);

    // Pt = WoT x WvH^T : Pt[m][n] = (Wv@Wo)[n][m], fp16 store
    gemm_h<<<dim3(H_/256, H_/128), 256, GSMEM_BYTES>>>(p_woT, p_wvH, p_PtH, H_, H_, H_, 0, 1, nullptr);
    // attn = n1c x Pt^T (fp32 out)
    gemm_h<<<dim3(H_/256, NTOK/128), 256, GSMEM_BYTES>>>(p_bufA, p_PtH, p_attn, NTOK, H_, H_, 1, 0, nullptr);
    // res + rmsnorm2
    res_kernel<<<NTOK, 256>>>(x, n2w, out);
    // gate / up projections (fp16 out)
    gemm_h<<<dim3(DFF_/256, NTOK/128), 256, GSMEM_BYTES>>>(p_bufA, p_wgT, p_gateH, NTOK, DFF_, H_, 1, 1, nullptr);
    gemm_h<<<dim3(DFF_/256, NTOK/128), 256, GSMEM_BYTES>>>(p_bufA, p_wuT, p_upH,   NTOK, DFF_, H_, 1, 1, nullptr);
    // h = fp16(silu(gate) * up)
    swiglu_kernel<<<(NTOK * (DFF_/2)) / 256, 256>>>();
    // out[selected] += h x wdT^T
    gemm_h<<<dim3(H_/256, NTOK/128), 256, GSMEM_BYTES>>>(p_hbuf, p_wdT, nullptr, NTOK, H_, DFF_, 1, 2, out);
}